// round 10
// baseline (speedup 1.0000x reference)
#include <cuda_runtime.h>
#include <cstdint>

#define VOCAB 100000
#define BATCH 2048
#define SEQ   50
#define HID   256
#define KIN   512

// ---------------- scratch (device globals; no allocation allowed) ----------
__device__ float g_bow_h[BATCH * HID];
__device__ float g_beo_h[BATCH * HID];
// epilogue K-split partials: [side*2+khalf][row][72] (64 embd + 5 pred + pad)
__device__ float g_part[2 * 2 * BATCH * 72];

__device__ __forceinline__ float lky(float v) {
    return (v > 0.f) ? v : 0.2f * v;
}

// ============================================================================
// K1: bow gather. 512 blocks x 256 threads, 4 rows/block, 64 thr/row,
// float4 direct gathers in 8-deep batches (register MLP).
// ============================================================================
#define G 4

__global__ __launch_bounds__(256) void bow_gather_kernel(
    const unsigned int* __restrict__ s_words,
    const float* __restrict__ Wh,
    const float* __restrict__ bh)
{
    __shared__ unsigned int wbuf[G * SEQ];
    __shared__ int   toks[G][SEQ];
    __shared__ float keep[G][SEQ];
    __shared__ int   sh_is64;

    const int tid   = threadIdx.x;
    const int wbase = blockIdx.x * (G * SEQ);   // even

    if (tid < G * SEQ) wbuf[tid] = s_words[wbase + tid];
    __syncthreads();

    if (tid == 0) {
        int all0 = 1;
        #pragma unroll
        for (int i = 1; i < G * SEQ; i += 2) all0 &= (wbuf[i] == 0u);
        sh_is64 = all0;
    }
    __syncthreads();

    const int is64 = sh_is64;
    if (tid < G * SEQ) {
        int r = tid / SEQ, j = tid - r * SEQ;
        toks[r][j] = is64 ? (int)s_words[2 * (wbase + tid)]
                          : (int)wbuf[tid];
    }
    __syncthreads();

    if (tid < G * SEQ) {
        int r = tid / SEQ, j = tid - r * SEQ;
        int t = toks[r][j];
        float k = 1.0f;
        for (int j2 = 0; j2 < j; j2++)
            if (toks[r][j2] == t) { k = 0.0f; break; }
        keep[r][j] = k;
    }
    __syncthreads();

    // gather-sum: 8-deep load batches, 4 rotating accumulators
    const int r  = tid >> 6;
    const int c4 = (tid & 63) * 4;
    const float* __restrict__ Wc = Wh + c4;

    float4 sa[4];
    #pragma unroll
    for (int q = 0; q < 4; q++) sa[q] = make_float4(0.f, 0.f, 0.f, 0.f);

    #pragma unroll
    for (int i = 0; i < 48; i += 8) {
        float4 v[8];
        float  kf[8];
        #pragma unroll
        for (int q = 0; q < 8; q++) {
            v[q]  = *(const float4*)(Wc + toks[r][i + q] * HID);
            kf[q] = keep[r][i + q];
        }
        #pragma unroll
        for (int q = 0; q < 8; q++) {
            float4& a = sa[q & 3];
            a.x = fmaf(kf[q], v[q].x, a.x);
            a.y = fmaf(kf[q], v[q].y, a.y);
            a.z = fmaf(kf[q], v[q].z, a.z);
            a.w = fmaf(kf[q], v[q].w, a.w);
        }
    }
    {   // tail 48, 49
        const float4 v0 = *(const float4*)(Wc + toks[r][48] * HID);
        const float4 v1 = *(const float4*)(Wc + toks[r][49] * HID);
        const float k0 = keep[r][48], k1 = keep[r][49];
        sa[0].x = fmaf(k0, v0.x, sa[0].x); sa[0].y = fmaf(k0, v0.y, sa[0].y);
        sa[0].z = fmaf(k0, v0.z, sa[0].z); sa[0].w = fmaf(k0, v0.w, sa[0].w);
        sa[1].x = fmaf(k1, v1.x, sa[1].x); sa[1].y = fmaf(k1, v1.y, sa[1].y);
        sa[1].z = fmaf(k1, v1.z, sa[1].z); sa[1].w = fmaf(k1, v1.w, sa[1].w);
    }

    const float4 bb = *(const float4*)(bh + c4);
    float o0 = (sa[0].x + sa[1].x) + (sa[2].x + sa[3].x) + bb.x;
    float o1 = (sa[0].y + sa[1].y) + (sa[2].y + sa[3].y) + bb.y;
    float o2 = (sa[0].z + sa[1].z) + (sa[2].z + sa[3].z) + bb.z;
    float o3 = (sa[0].w + sa[1].w) + (sa[2].w + sa[3].w) + bb.w;
    *(float4*)&g_bow_h[(blockIdx.x * G + r) * HID + c4] =
        make_float4(lky(o0), lky(o1), lky(o2), lky(o3));
}

// ============================================================================
// K2: beo GEMM. BM=64, BN=64, BK=32; 128 blocks x 256 threads. (known good)
// ============================================================================
#define BM 64
#define BN 64
#define BK 32

__global__ __launch_bounds__(256) void beo_gemm_kernel(
    const float* __restrict__ X, const float* __restrict__ W,
    const float* __restrict__ bias)
{
    __shared__ __align__(16) float As[BM][BK + 4];
    __shared__ __align__(16) float Bs[BK][BN];

    const int tid = threadIdx.x;
    const int bx  = blockIdx.x;
    const int m0  = (bx >> 2) * BM;
    const int n0  = (bx & 3) * BN;
    const int tx  = tid & 15;
    const int ty  = tid >> 4;

    unsigned long long acc[4][2];
    #pragma unroll
    for (int r = 0; r < 4; r++) { acc[r][0] = 0ull; acc[r][1] = 0ull; }

    for (int k0 = 0; k0 < KIN; k0 += BK) {
        #pragma unroll
        for (int f = tid; f < BM * BK / 4; f += 256) {
            int r = f >> 3, q = f & 7;
            *(float4*)&As[r][q * 4] =
                *(const float4*)&X[(m0 + r) * KIN + k0 + q * 4];
        }
        #pragma unroll
        for (int f = tid; f < BK * BN / 4; f += 256) {
            int kr = f >> 4, nq = f & 15;
            *(float4*)&Bs[kr][nq * 4] =
                *(const float4*)&W[(k0 + kr) * HID + n0 + nq * 4];
        }
        __syncthreads();

        #pragma unroll
        for (int k = 0; k < BK; k++) {
            float4 bv = *(const float4*)&Bs[k][tx * 4];
            unsigned long long pb0, pb1;
            asm("mov.b64 %0, {%1, %2};" : "=l"(pb0) : "f"(bv.x), "f"(bv.y));
            asm("mov.b64 %0, {%1, %2};" : "=l"(pb1) : "f"(bv.z), "f"(bv.w));
            #pragma unroll
            for (int r = 0; r < 4; r++) {
                float av = As[ty * 4 + r][k];
                unsigned long long pa;
                asm("mov.b64 %0, {%1, %1};" : "=l"(pa) : "f"(av));
                asm("fma.rn.f32x2 %0, %1, %2, %0;" : "+l"(acc[r][0]) : "l"(pa), "l"(pb0));
                asm("fma.rn.f32x2 %0, %1, %2, %0;" : "+l"(acc[r][1]) : "l"(pa), "l"(pb1));
            }
        }
        __syncthreads();
    }

    const float4 bb = *(const float4*)&bias[n0 + tx * 4];
    #pragma unroll
    for (int r = 0; r < 4; r++) {
        float o0, o1, o2, o3;
        asm("mov.b64 {%0, %1}, %2;" : "=f"(o0), "=f"(o1) : "l"(acc[r][0]));
        asm("mov.b64 {%0, %1}, %2;" : "=f"(o2), "=f"(o3) : "l"(acc[r][1]));
        *(float4*)&g_beo_h[(m0 + ty * 4 + r) * HID + n0 + tx * 4] =
            make_float4(lky(o0 + bb.x), lky(o1 + bb.y),
                        lky(o2 + bb.z), lky(o3 + bb.w));
    }
}

// ============================================================================
// K3: epilogue with K-split, ONE side per launch. grid (128, 2 khalf).
// ============================================================================
#define EPB 16
#define HP  20

union EpSmem {
    float WeS[128][64];
    struct {
        float red[4][EPB][64];
        float predred[EPB * 10];
    } r;
};

__global__ __launch_bounds__(256) void epilogue_kernel(
    const float* __restrict__ We, const float* __restrict__ Wp, int side)
{
    __shared__ __align__(16) float sh_t[128][HP];
    __shared__ EpSmem u;

    const int kh   = blockIdx.y;
    const int row0 = blockIdx.x * EPB;
    const int tid  = threadIdx.x;
    const int kg0  = kh * 128;

    const float* H = side ? g_beo_h : g_bow_h;

    #pragma unroll
    for (int f = tid; f < EPB * 32; f += 256) {
        int r = f & 15, cq = f >> 4;
        float4 v = *(const float4*)&H[(row0 + r) * HID + kg0 + cq * 4];
        sh_t[cq * 4 + 0][r] = v.x;
        sh_t[cq * 4 + 1][r] = v.y;
        sh_t[cq * 4 + 2][r] = v.z;
        sh_t[cq * 4 + 3][r] = v.w;
    }
    #pragma unroll
    for (int f = tid; f < 128 * 16; f += 256) {
        int kr = f >> 4, nq = f & 15;
        *(float4*)&u.WeS[kr][nq * 4] =
            *(const float4*)&We[(kg0 + kr) * 64 + nq * 4];
    }
    __syncthreads();

    const int cg = tid & 15;
    const int rg = (tid >> 4) & 3;
    const int kp = tid >> 6;

    unsigned long long acc[4][2];
    #pragma unroll
    for (int r = 0; r < 4; r++) { acc[r][0] = 0ull; acc[r][1] = 0ull; }

    #pragma unroll 8
    for (int k = 0; k < 32; k++) {
        const int kk = kp * 32 + k;
        float4 hv = *(const float4*)&sh_t[kk][rg * 4];
        float4 wv = *(const float4*)&u.WeS[kk][cg * 4];
        unsigned long long pw0, pw1;
        asm("mov.b64 %0, {%1, %2};" : "=l"(pw0) : "f"(wv.x), "f"(wv.y));
        asm("mov.b64 %0, {%1, %2};" : "=l"(pw1) : "f"(wv.z), "f"(wv.w));
        unsigned long long ph0, ph1, ph2, ph3;
        asm("mov.b64 %0, {%1, %1};" : "=l"(ph0) : "f"(hv.x));
        asm("mov.b64 %0, {%1, %1};" : "=l"(ph1) : "f"(hv.y));
        asm("mov.b64 %0, {%1, %1};" : "=l"(ph2) : "f"(hv.z));
        asm("mov.b64 %0, {%1, %1};" : "=l"(ph3) : "f"(hv.w));
        asm("fma.rn.f32x2 %0, %1, %2, %0;" : "+l"(acc[0][0]) : "l"(ph0), "l"(pw0));
        asm("fma.rn.f32x2 %0, %1, %2, %0;" : "+l"(acc[0][1]) : "l"(ph0), "l"(pw1));
        asm("fma.rn.f32x2 %0, %1, %2, %0;" : "+l"(acc[1][0]) : "l"(ph1), "l"(pw0));
        asm("fma.rn.f32x2 %0, %1, %2, %0;" : "+l"(acc[1][1]) : "l"(ph1), "l"(pw1));
        asm("fma.rn.f32x2 %0, %1, %2, %0;" : "+l"(acc[2][0]) : "l"(ph2), "l"(pw0));
        asm("fma.rn.f32x2 %0, %1, %2, %0;" : "+l"(acc[2][1]) : "l"(ph2), "l"(pw1));
        asm("fma.rn.f32x2 %0, %1, %2, %0;" : "+l"(acc[3][0]) : "l"(ph3), "l"(pw0));
        asm("fma.rn.f32x2 %0, %1, %2, %0;" : "+l"(acc[3][1]) : "l"(ph3), "l"(pw1));
    }
    __syncthreads();

    #pragma unroll
    for (int r = 0; r < 4; r++) {
        float a0, a1, a2, a3;
        asm("mov.b64 {%0, %1}, %2;" : "=f"(a0), "=f"(a1) : "l"(acc[r][0]));
        asm("mov.b64 {%0, %1}, %2;" : "=f"(a2), "=f"(a3) : "l"(acc[r][1]));
        *(float4*)&u.r.red[kp][rg * 4 + r][cg * 4] = make_float4(a0, a1, a2, a3);
    }

    if (tid < EPB * 10) {
        int r   = tid / 10;
        int rem = tid - r * 10;
        int j   = rem % 5;
        int kq  = rem / 5;
        const int kb = kq * 64;
        float a0 = 0.f, a1 = 0.f, a2 = 0.f, a3 = 0.f;
        #pragma unroll 4
        for (int k = 0; k < 64; k += 4) {
            a0 = fmaf(sh_t[kb + k + 0][r], Wp[(kg0 + kb + k + 0) * 5 + j], a0);
            a1 = fmaf(sh_t[kb + k + 1][r], Wp[(kg0 + kb + k + 1) * 5 + j], a1);
            a2 = fmaf(sh_t[kb + k + 2][r], Wp[(kg0 + kb + k + 2) * 5 + j], a2);
            a3 = fmaf(sh_t[kb + k + 3][r], Wp[(kg0 + kb + k + 3) * 5 + j], a3);
        }
        u.r.predred[tid] = (a0 + a1) + (a2 + a3);
    }
    __syncthreads();

    float* P = &g_part[((size_t)(side * 2 + kh) * BATCH) * 72];
    {
        const int rr = tid >> 4;
        const int c4 = (tid & 15) * 4;
        float4 p0 = *(const float4*)&u.r.red[0][rr][c4];
        float4 p1 = *(const float4*)&u.r.red[1][rr][c4];
        float4 p2 = *(const float4*)&u.r.red[2][rr][c4];
        float4 p3 = *(const float4*)&u.r.red[3][rr][c4];
        *(float4*)&P[(row0 + rr) * 72 + c4] =
            make_float4((p0.x + p1.x) + (p2.x + p3.x),
                        (p0.y + p1.y) + (p2.y + p3.y),
                        (p0.z + p1.z) + (p2.z + p3.z),
                        (p0.w + p1.w) + (p2.w + p3.w));
    }
    if (tid < EPB * 5) {
        int r = tid / 5, j = tid - r * 5;
        P[(row0 + r) * 72 + 64 + j] =
            u.r.predred[r * 10 + j] + u.r.predred[r * 10 + 5 + j];
    }
}

// ============================================================================
// Combine (one side): out = part[kh0] + part[kh1] + bias. grid 552.
// ============================================================================
__global__ __launch_bounds__(256) void combine_kernel(
    const float* __restrict__ be, const float* __restrict__ bp,
    int side, float* __restrict__ out)
{
    const int e = blockIdx.x * 256 + threadIdx.x;
    if (e >= BATCH * 69) return;

    const float* P0 = &g_part[((size_t)(side * 2 + 0) * BATCH) * 72];
    const float* P1 = &g_part[((size_t)(side * 2 + 1) * BATCH) * 72];

    if (e < BATCH * 64) {
        int row = e >> 6, c = e & 63;
        out[(side ? BATCH * 64 : 0) + e] =
            P0[row * 72 + c] + P1[row * 72 + c] + be[c];
    } else {
        int e2 = e - BATCH * 64;
        int row = e2 / 5, j = e2 - row * 5;
        out[BATCH * 128 + side * BATCH * 5 + e2] =
            P0[row * 72 + 64 + j] + P1[row * 72 + 64 + j] + bp[j];
    }
}

// ============================================================================
extern "C" void kernel_launch(void* const* d_in, const int* in_sizes, int n_in,
                              void* d_out, int out_size)
{
    const unsigned int* s_words = (const unsigned int*)d_in[0];
    const float* x        = (const float*)d_in[1];
    const float* W_bow_h  = (const float*)d_in[2];
    const float* b_bow_h  = (const float*)d_in[3];
    const float* W_bow_p  = (const float*)d_in[4];
    const float* b_bow_p  = (const float*)d_in[5];
    const float* W_bow_e  = (const float*)d_in[6];
    const float* b_bow_e  = (const float*)d_in[7];
    const float* W_beo_h  = (const float*)d_in[8];
    const float* b_beo_h  = (const float*)d_in[9];
    const float* W_beo_p  = (const float*)d_in[10];
    const float* b_beo_p  = (const float*)d_in[11];
    const float* W_beo_e  = (const float*)d_in[12];
    const float* b_beo_e  = (const float*)d_in[13];
    float* out = (float*)d_out;

    // one-time stream/event setup (no device memory involved)
    static int init_done = 0;
    static int use_streams = 0;
    static cudaStream_t s1;
    static cudaEvent_t evF, evJ;
    if (!init_done) {
        use_streams = 1;
        if (cudaStreamCreateWithFlags(&s1, cudaStreamNonBlocking) != cudaSuccess)
            use_streams = 0;
        if (use_streams &&
            cudaEventCreateWithFlags(&evF, cudaEventDisableTiming) != cudaSuccess)
            use_streams = 0;
        if (use_streams &&
            cudaEventCreateWithFlags(&evJ, cudaEventDisableTiming) != cudaSuccess)
            use_streams = 0;
        init_done = 1;
    }

    const cudaStream_t sB = use_streams ? s1 : (cudaStream_t)0;

    if (use_streams) {
        cudaEventRecord(evF, 0);            // fork from the captured stream
        cudaStreamWaitEvent(s1, evF, 0);
    }

    // main stream: bow chain (critical path)
    bow_gather_kernel<<<BATCH / G, 256, 0, 0>>>(s_words, W_bow_h, b_bow_h);

    // side stream: beo chain
    beo_gemm_kernel<<<128, 256, 0, sB>>>(x, W_beo_h, b_beo_h);
    {
        dim3 ge(BATCH / EPB, 2);
        epilogue_kernel<<<ge, 256, 0, sB>>>(W_beo_e, W_beo_p, 1);
        combine_kernel<<<(BATCH * 69 + 255) / 256, 256, 0, sB>>>(
            b_beo_e, b_beo_p, 1, out);
    }
    if (use_streams) cudaEventRecord(evJ, s1);

    // main stream continues: bow epilogue + combine
    {
        dim3 ge(BATCH / EPB, 2);
        epilogue_kernel<<<ge, 256, 0, 0>>>(W_bow_e, W_bow_p, 0);
        combine_kernel<<<(BATCH * 69 + 255) / 256, 256, 0, 0>>>(
            b_bow_e, b_bow_p, 0, out);
    }

    if (use_streams) cudaStreamWaitEvent(0, evJ, 0);   // join
}

// round 11
// speedup vs baseline: 1.6181x; 1.6181x over previous
#include <cuda_runtime.h>
#include <cstdint>

#define VOCAB 100000
#define BATCH 2048
#define SEQ   50
#define HID   256
#define KIN   512

// ---------------- scratch (device globals; no allocation allowed) ----------
__device__ float g_bow_h[BATCH * HID];
__device__ float g_beo_h[BATCH * HID];

__device__ __forceinline__ float lky(float v) {
    return (v > 0.f) ? v : 0.2f * v;
}

// ============================================================================
// Fused kernel (verbatim round 7, measured ~35us): blocks [0, K2_BLOCKS) do
// the beo GEMM; blocks [K2_BLOCKS, +K1_BLOCKS) do the bow gather. 256 thr.
// ============================================================================
#define BM 64
#define BN 64
#define BK 32
#define K2_BLOCKS ((BATCH / BM) * (HID / BN))   // 128
#define K1_ROWS_PER_BLK 2
#define K1_BLOCKS (BATCH / K1_ROWS_PER_BLK)     // 1024

union SmemU {
    struct {                       // GEMM tiles
        float As[BM][BK + 4];
        float Bs[BK][BN];
    } g;
    struct {                       // bow gather scratch
        unsigned int wbuf[K1_ROWS_PER_BLK * SEQ];
        int   toks[K1_ROWS_PER_BLK][SEQ];
        float keep[K1_ROWS_PER_BLK][SEQ];
        float part[K1_ROWS_PER_BLK][HID];
        int   is64;
    } b;
};

__global__ __launch_bounds__(256) void fused_hidden_kernel(
    const unsigned int* __restrict__ s_words,
    const float* __restrict__ Wh,    const float* __restrict__ bh,
    const float* __restrict__ X,     const float* __restrict__ W,
    const float* __restrict__ bias)
{
    __shared__ SmemU sm;
    const int tid = threadIdx.x;

    if (blockIdx.x < K2_BLOCKS) {
        // ------------------------- beo GEMM path ---------------------------
        const int bx = blockIdx.x;
        const int m0 = (bx >> 2) * BM;
        const int n0 = (bx & 3) * BN;
        const int tx = tid & 15;
        const int ty = tid >> 4;

        unsigned long long acc[4][2];
        #pragma unroll
        for (int r = 0; r < 4; r++) { acc[r][0] = 0ull; acc[r][1] = 0ull; }

        for (int k0 = 0; k0 < KIN; k0 += BK) {
            #pragma unroll
            for (int f = tid; f < BM * BK / 4; f += 256) {
                int r = f >> 3, q = f & 7;
                *(float4*)&sm.g.As[r][q * 4] =
                    *(const float4*)&X[(m0 + r) * KIN + k0 + q * 4];
            }
            #pragma unroll
            for (int f = tid; f < BK * BN / 4; f += 256) {
                int kr = f >> 4, nq = f & 15;
                *(float4*)&sm.g.Bs[kr][nq * 4] =
                    *(const float4*)&W[(k0 + kr) * HID + n0 + nq * 4];
            }
            __syncthreads();

            #pragma unroll
            for (int k = 0; k < BK; k++) {
                float4 bv = *(const float4*)&sm.g.Bs[k][tx * 4];
                unsigned long long pb0, pb1;
                asm("mov.b64 %0, {%1, %2};" : "=l"(pb0) : "f"(bv.x), "f"(bv.y));
                asm("mov.b64 %0, {%1, %2};" : "=l"(pb1) : "f"(bv.z), "f"(bv.w));
                #pragma unroll
                for (int r = 0; r < 4; r++) {
                    float av = sm.g.As[ty * 4 + r][k];
                    unsigned long long pa;
                    asm("mov.b64 %0, {%1, %1};" : "=l"(pa) : "f"(av));
                    asm("fma.rn.f32x2 %0, %1, %2, %0;" : "+l"(acc[r][0]) : "l"(pa), "l"(pb0));
                    asm("fma.rn.f32x2 %0, %1, %2, %0;" : "+l"(acc[r][1]) : "l"(pa), "l"(pb1));
                }
            }
            __syncthreads();
        }

        const float4 bb = *(const float4*)&bias[n0 + tx * 4];
        #pragma unroll
        for (int r = 0; r < 4; r++) {
            float o0, o1, o2, o3;
            asm("mov.b64 {%0, %1}, %2;" : "=f"(o0), "=f"(o1) : "l"(acc[r][0]));
            asm("mov.b64 {%0, %1}, %2;" : "=f"(o2), "=f"(o3) : "l"(acc[r][1]));
            *(float4*)&g_beo_h[(m0 + ty * 4 + r) * HID + n0 + tx * 4] =
                make_float4(lky(o0 + bb.x), lky(o1 + bb.y),
                            lky(o2 + bb.z), lky(o3 + bb.w));
        }
    } else {
        // ------------------------- bow gather path -------------------------
        const int kb    = blockIdx.x - K2_BLOCKS;
        const int wbase = kb * (K1_ROWS_PER_BLK * SEQ);

        if (tid < K1_ROWS_PER_BLK * SEQ) sm.b.wbuf[tid] = s_words[wbase + tid];
        __syncthreads();

        if (tid == 0) {
            int all0 = 1;
            #pragma unroll
            for (int i = 1; i < K1_ROWS_PER_BLK * SEQ; i += 2)
                all0 &= (sm.b.wbuf[i] == 0u);
            sm.b.is64 = all0;
        }
        __syncthreads();

        const int is64 = sm.b.is64;
        if (tid < K1_ROWS_PER_BLK * SEQ) {
            int r = tid / SEQ, j = tid - r * SEQ;
            sm.b.toks[r][j] = is64 ? (int)s_words[2 * (wbase + tid)]
                                   : (int)sm.b.wbuf[tid];
        }
        __syncthreads();

        if (tid < K1_ROWS_PER_BLK * SEQ) {
            int r = tid / SEQ, j = tid - r * SEQ;
            int t = sm.b.toks[r][j];
            float k = 1.0f;
            for (int j2 = 0; j2 < j; j2++)
                if (sm.b.toks[r][j2] == t) { k = 0.0f; break; }
            sm.b.keep[r][j] = k;
        }
        __syncthreads();

        // gather: 2 rows x 2 halves x 64 col-threads; 8-deep load batches
        const int r    = tid >> 7;
        const int h    = (tid >> 6) & 1;
        const int c4   = (tid & 63) * 4;
        const int jb   = h * (SEQ / 2);       // 25 tokens per half
        const float* __restrict__ Wc = Wh + c4;

        float4 sa[8];
        #pragma unroll
        for (int q = 0; q < 8; q++) sa[q] = make_float4(0.f, 0.f, 0.f, 0.f);

        #pragma unroll
        for (int i = 0; i < 24; i += 8) {
            float4 v[8];
            float  kf[8];
            #pragma unroll
            for (int q = 0; q < 8; q++) {
                v[q]  = *(const float4*)(Wc + sm.b.toks[r][jb + i + q] * HID);
                kf[q] = sm.b.keep[r][jb + i + q];
            }
            #pragma unroll
            for (int q = 0; q < 8; q++) {
                sa[q].x = fmaf(kf[q], v[q].x, sa[q].x);
                sa[q].y = fmaf(kf[q], v[q].y, sa[q].y);
                sa[q].z = fmaf(kf[q], v[q].z, sa[q].z);
                sa[q].w = fmaf(kf[q], v[q].w, sa[q].w);
            }
        }
        {   // tail token (i = 24)
            const float4 v = *(const float4*)(Wc + sm.b.toks[r][jb + 24] * HID);
            const float kf = sm.b.keep[r][jb + 24];
            sa[0].x = fmaf(kf, v.x, sa[0].x); sa[0].y = fmaf(kf, v.y, sa[0].y);
            sa[0].z = fmaf(kf, v.z, sa[0].z); sa[0].w = fmaf(kf, v.w, sa[0].w);
        }

        float4 t;
        t.x = ((sa[0].x + sa[1].x) + (sa[2].x + sa[3].x)) +
              ((sa[4].x + sa[5].x) + (sa[6].x + sa[7].x));
        t.y = ((sa[0].y + sa[1].y) + (sa[2].y + sa[3].y)) +
              ((sa[4].y + sa[5].y) + (sa[6].y + sa[7].y));
        t.z = ((sa[0].z + sa[1].z) + (sa[2].z + sa[3].z)) +
              ((sa[4].z + sa[5].z) + (sa[6].z + sa[7].z));
        t.w = ((sa[0].w + sa[1].w) + (sa[2].w + sa[3].w)) +
              ((sa[4].w + sa[5].w) + (sa[6].w + sa[7].w));

        if (h == 1) *(float4*)&sm.b.part[r][c4] = t;
        __syncthreads();
        if (h == 0) {
            const float4 p  = *(const float4*)&sm.b.part[r][c4];
            const float4 bb = *(const float4*)(bh + c4);
            *(float4*)&g_bow_h[(kb * K1_ROWS_PER_BLK + r) * HID + c4] =
                make_float4(lky(t.x + p.x + bb.x), lky(t.y + p.y + bb.y),
                            lky(t.z + p.z + bb.z), lky(t.w + p.w + bb.w));
        }
    }
}

// ============================================================================
// K3 v6: N-SPLIT epilogue, no combine kernel. grid (128, 2 sides, 2 nhalf)
// = 512 blocks x 256 threads. Each block: 16 rows x 32 cols over full K=256,
// K split 8-ways INSIDE the block (reduced via smem). Writes out + bias
// directly. Pred (5 cols, full K) handled by nh==0 blocks.
// ============================================================================
#define EPB 16
#define HP  20                                  // padded transposed-H stride

union EpSmem {
    float WeS[HID][32];                         // 32 KB: We cols half
    struct {
        float red[8][EPB][32];                  // 16 KB embd kp-partials
        float predred[EPB * 10];                // pred partials
    } r;
};

__global__ __launch_bounds__(256) void epilogue_kernel(
    const float* __restrict__ We_bow, const float* __restrict__ be_bow,
    const float* __restrict__ Wp_bow, const float* __restrict__ bp_bow,
    const float* __restrict__ We_beo, const float* __restrict__ be_beo,
    const float* __restrict__ Wp_beo, const float* __restrict__ bp_beo,
    float* __restrict__ out)
{
    __shared__ __align__(16) float sh_t[HID][HP];   // 20 KB transposed H
    __shared__ EpSmem u;

    const int side = blockIdx.y;
    const int nh   = blockIdx.z;                    // N half: cols [nh*32, +32)
    const int row0 = blockIdx.x * EPB;
    const int tid  = threadIdx.x;
    const int n0   = nh * 32;

    const float* H  = side ? g_beo_h : g_bow_h;
    const float* We = side ? We_beo : We_bow;
    const float* be = side ? be_beo : be_bow;
    const float* Wp = side ? Wp_beo : Wp_bow;
    const float* bp = side ? bp_beo : bp_bow;

    // stage H transposed: 16 rows x 64 colquads = 1024 float4 / 256 = 4 each
    #pragma unroll
    for (int f = tid; f < EPB * (HID / 4); f += 256) {
        int r = f & 15, cq = f >> 4;
        float4 v = *(const float4*)&H[(row0 + r) * HID + cq * 4];
        sh_t[cq * 4 + 0][r] = v.x;
        sh_t[cq * 4 + 1][r] = v.y;
        sh_t[cq * 4 + 2][r] = v.z;
        sh_t[cq * 4 + 3][r] = v.w;
    }
    // stage We column half: 256 k x 8 quads = 2048 float4 / 256 = 8 each
    #pragma unroll
    for (int f = tid; f < HID * 8; f += 256) {
        int kr = f >> 3, nq = f & 7;
        *(float4*)&u.WeS[kr][nq * 4] =
            *(const float4*)&We[kr * 64 + n0 + nq * 4];
    }
    __syncthreads();

    const int cg = tid & 7;            // 8 col groups * 4 cols = 32
    const int rg = (tid >> 3) & 3;     // 4 row groups * 4 rows = 16
    const int kp = tid >> 5;           // 8 K partitions * 32 k

    unsigned long long acc[4][2];
    #pragma unroll
    for (int r = 0; r < 4; r++) { acc[r][0] = 0ull; acc[r][1] = 0ull; }

    #pragma unroll 8
    for (int k = 0; k < 32; k++) {
        const int kk = kp * 32 + k;
        float4 hv = *(const float4*)&sh_t[kk][rg * 4];
        float4 wv = *(const float4*)&u.WeS[kk][cg * 4];
        unsigned long long pw0, pw1;
        asm("mov.b64 %0, {%1, %2};" : "=l"(pw0) : "f"(wv.x), "f"(wv.y));
        asm("mov.b64 %0, {%1, %2};" : "=l"(pw1) : "f"(wv.z), "f"(wv.w));
        unsigned long long ph0, ph1, ph2, ph3;
        asm("mov.b64 %0, {%1, %1};" : "=l"(ph0) : "f"(hv.x));
        asm("mov.b64 %0, {%1, %1};" : "=l"(ph1) : "f"(hv.y));
        asm("mov.b64 %0, {%1, %1};" : "=l"(ph2) : "f"(hv.z));
        asm("mov.b64 %0, {%1, %1};" : "=l"(ph3) : "f"(hv.w));
        asm("fma.rn.f32x2 %0, %1, %2, %0;" : "+l"(acc[0][0]) : "l"(ph0), "l"(pw0));
        asm("fma.rn.f32x2 %0, %1, %2, %0;" : "+l"(acc[0][1]) : "l"(ph0), "l"(pw1));
        asm("fma.rn.f32x2 %0, %1, %2, %0;" : "+l"(acc[1][0]) : "l"(ph1), "l"(pw0));
        asm("fma.rn.f32x2 %0, %1, %2, %0;" : "+l"(acc[1][1]) : "l"(ph1), "l"(pw1));
        asm("fma.rn.f32x2 %0, %1, %2, %0;" : "+l"(acc[2][0]) : "l"(ph2), "l"(pw0));
        asm("fma.rn.f32x2 %0, %1, %2, %0;" : "+l"(acc[2][1]) : "l"(ph2), "l"(pw1));
        asm("fma.rn.f32x2 %0, %1, %2, %0;" : "+l"(acc[3][0]) : "l"(ph3), "l"(pw0));
        asm("fma.rn.f32x2 %0, %1, %2, %0;" : "+l"(acc[3][1]) : "l"(ph3), "l"(pw1));
    }
    __syncthreads();   // done reading WeS; union reused below

    // ---- deposit embd kp-partials ----
    #pragma unroll
    for (int r = 0; r < 4; r++) {
        float a0, a1, a2, a3;
        asm("mov.b64 {%0, %1}, %2;" : "=f"(a0), "=f"(a1) : "l"(acc[r][0]));
        asm("mov.b64 {%0, %1}, %2;" : "=f"(a2), "=f"(a3) : "l"(acc[r][1]));
        *(float4*)&u.r.red[kp][rg * 4 + r][cg * 4] = make_float4(a0, a1, a2, a3);
    }

    // ---- pred partials (nh==0 blocks only): 160 threads, K-split-2 ----
    if (nh == 0 && tid < EPB * 10) {
        int r   = tid / 10;
        int rem = tid - r * 10;
        int j   = rem % 5;
        int kq  = rem / 5;
        const int kb = kq * 128;
        float a0 = 0.f, a1 = 0.f, a2 = 0.f, a3 = 0.f;
        #pragma unroll 4
        for (int k = 0; k < 128; k += 4) {
            a0 = fmaf(sh_t[kb + k + 0][r], Wp[(kb + k + 0) * 5 + j], a0);
            a1 = fmaf(sh_t[kb + k + 1][r], Wp[(kb + k + 1) * 5 + j], a1);
            a2 = fmaf(sh_t[kb + k + 2][r], Wp[(kb + k + 2) * 5 + j], a2);
            a3 = fmaf(sh_t[kb + k + 3][r], Wp[(kb + k + 3) * 5 + j], a3);
        }
        u.r.predred[tid] = (a0 + a1) + (a2 + a3);
    }
    __syncthreads();

    // ---- final: sum 8 kp-partials + bias, write out directly ----
    {
        // 512 outputs / 256 threads = 2 each (two row groups)
        const int c  = tid & 31;          // col within half
        const int r0 = tid >> 5;          // 8 row slots -> rows r0, r0+8
        #pragma unroll
        for (int rr = r0; rr < EPB; rr += 8) {
            float s = 0.f;
            #pragma unroll
            for (int q = 0; q < 8; q++) s += u.r.red[q][rr][c];
            const int ebase = side ? (BATCH * 64) : 0;
            out[ebase + (row0 + rr) * 64 + n0 + c] = s + be[n0 + c];
        }
    }
    if (nh == 0 && tid < EPB * 5) {
        int r = tid / 5, j = tid - r * 5;
        float v = u.r.predred[r * 10 + j] + u.r.predred[r * 10 + 5 + j] + bp[j];
        const int pbase = BATCH * 128 + (side ? BATCH * 5 : 0);
        out[pbase + (row0 + r) * 5 + j] = v;
    }
}

// ============================================================================
extern "C" void kernel_launch(void* const* d_in, const int* in_sizes, int n_in,
                              void* d_out, int out_size)
{
    const unsigned int* s_words = (const unsigned int*)d_in[0];
    const float* x        = (const float*)d_in[1];
    const float* W_bow_h  = (const float*)d_in[2];
    const float* b_bow_h  = (const float*)d_in[3];
    const float* W_bow_p  = (const float*)d_in[4];
    const float* b_bow_p  = (const float*)d_in[5];
    const float* W_bow_e  = (const float*)d_in[6];
    const float* b_bow_e  = (const float*)d_in[7];
    const float* W_beo_h  = (const float*)d_in[8];
    const float* b_beo_h  = (const float*)d_in[9];
    const float* W_beo_p  = (const float*)d_in[10];
    const float* b_beo_p  = (const float*)d_in[11];
    const float* W_beo_e  = (const float*)d_in[12];
    const float* b_beo_e  = (const float*)d_in[13];
    float* out = (float*)d_out;

    fused_hidden_kernel<<<K2_BLOCKS + K1_BLOCKS, 256>>>(
        s_words, W_bow_h, b_bow_h, x, W_beo_h, b_beo_h);

    dim3 g3(BATCH / EPB, 2, 2);
    epilogue_kernel<<<g3, 256>>>(W_bow_e, b_bow_e, W_bow_p, b_bow_p,
                                 W_beo_e, b_beo_e, W_beo_p, b_beo_p, out);
}

// round 13
// speedup vs baseline: 1.6200x; 1.0012x over previous
#include <cuda_runtime.h>
#include <cstdint>

#define VOCAB 100000
#define BATCH 2048
#define SEQ   50
#define HID   256
#define KIN   512

// ---------------- scratch (device globals; no allocation allowed) ----------
__device__ float g_bow_h[BATCH * HID];
__device__ float g_beo_h[BATCH * HID];
// epilogue K-split partials: [side*2+khalf][row][72] (64 embd + 5 pred + pad)
__device__ float g_part[2 * 2 * BATCH * 72];

__device__ __forceinline__ float lky(float v) {
    return (v > 0.f) ? v : 0.2f * v;
}

// build an evict_last L2 policy register (once per thread)
__device__ __forceinline__ unsigned long long mk_policy_el() {
    unsigned long long pol;
    asm("createpolicy.fractional.L2::evict_last.b64 %0, 1.0;" : "=l"(pol));
    return pol;
}

// table gather load: float4 via L2::cache_hint with evict_last policy
__device__ __forceinline__ float4 ldg_el(const float* p, unsigned long long pol) {
    float4 v;
    asm("ld.global.nc.L2::cache_hint.v4.f32 {%0, %1, %2, %3}, [%4], %5;"
        : "=f"(v.x), "=f"(v.y), "=f"(v.z), "=f"(v.w) : "l"(p), "l"(pol));
    return v;
}

// ============================================================================
// Fused kernel (round-7 structure, measured ~35us): blocks [0, K2_BLOCKS)
// beo GEMM; blocks [K2_BLOCKS, +K1_BLOCKS) bow gather. 256 threads.
// Gather loads carry an evict_last cache policy.
// ============================================================================
#define BM 64
#define BN 64
#define BK 32
#define K2_BLOCKS ((BATCH / BM) * (HID / BN))   // 128
#define K1_ROWS_PER_BLK 2
#define K1_BLOCKS (BATCH / K1_ROWS_PER_BLK)     // 1024

union SmemU {
    struct {                       // GEMM tiles
        float As[BM][BK + 4];
        float Bs[BK][BN];
    } g;
    struct {                       // bow gather scratch
        unsigned int wbuf[K1_ROWS_PER_BLK * SEQ];
        int   toks[K1_ROWS_PER_BLK][SEQ];
        float keep[K1_ROWS_PER_BLK][SEQ];
        float part[K1_ROWS_PER_BLK][HID];
        int   is64;
    } b;
};

__global__ __launch_bounds__(256) void fused_hidden_kernel(
    const unsigned int* __restrict__ s_words,
    const float* __restrict__ Wh,    const float* __restrict__ bh,
    const float* __restrict__ X,     const float* __restrict__ W,
    const float* __restrict__ bias)
{
    __shared__ SmemU sm;
    const int tid = threadIdx.x;

    if (blockIdx.x < K2_BLOCKS) {
        // ------------------------- beo GEMM path ---------------------------
        const int bx = blockIdx.x;
        const int m0 = (bx >> 2) * BM;
        const int n0 = (bx & 3) * BN;
        const int tx = tid & 15;
        const int ty = tid >> 4;

        unsigned long long acc[4][2];
        #pragma unroll
        for (int r = 0; r < 4; r++) { acc[r][0] = 0ull; acc[r][1] = 0ull; }

        for (int k0 = 0; k0 < KIN; k0 += BK) {
            #pragma unroll
            for (int f = tid; f < BM * BK / 4; f += 256) {
                int r = f >> 3, q = f & 7;
                *(float4*)&sm.g.As[r][q * 4] =
                    *(const float4*)&X[(m0 + r) * KIN + k0 + q * 4];
            }
            #pragma unroll
            for (int f = tid; f < BK * BN / 4; f += 256) {
                int kr = f >> 4, nq = f & 15;
                *(float4*)&sm.g.Bs[kr][nq * 4] =
                    *(const float4*)&W[(k0 + kr) * HID + n0 + nq * 4];
            }
            __syncthreads();

            #pragma unroll
            for (int k = 0; k < BK; k++) {
                float4 bv = *(const float4*)&sm.g.Bs[k][tx * 4];
                unsigned long long pb0, pb1;
                asm("mov.b64 %0, {%1, %2};" : "=l"(pb0) : "f"(bv.x), "f"(bv.y));
                asm("mov.b64 %0, {%1, %2};" : "=l"(pb1) : "f"(bv.z), "f"(bv.w));
                #pragma unroll
                for (int r = 0; r < 4; r++) {
                    float av = sm.g.As[ty * 4 + r][k];
                    unsigned long long pa;
                    asm("mov.b64 %0, {%1, %1};" : "=l"(pa) : "f"(av));
                    asm("fma.rn.f32x2 %0, %1, %2, %0;" : "+l"(acc[r][0]) : "l"(pa), "l"(pb0));
                    asm("fma.rn.f32x2 %0, %1, %2, %0;" : "+l"(acc[r][1]) : "l"(pa), "l"(pb1));
                }
            }
            __syncthreads();
        }

        const float4 bb = *(const float4*)&bias[n0 + tx * 4];
        #pragma unroll
        for (int r = 0; r < 4; r++) {
            float o0, o1, o2, o3;
            asm("mov.b64 {%0, %1}, %2;" : "=f"(o0), "=f"(o1) : "l"(acc[r][0]));
            asm("mov.b64 {%0, %1}, %2;" : "=f"(o2), "=f"(o3) : "l"(acc[r][1]));
            *(float4*)&g_beo_h[(m0 + ty * 4 + r) * HID + n0 + tx * 4] =
                make_float4(lky(o0 + bb.x), lky(o1 + bb.y),
                            lky(o2 + bb.z), lky(o3 + bb.w));
        }
    } else {
        // ------------------------- bow gather path -------------------------
        const int kb    = blockIdx.x - K2_BLOCKS;
        const int wbase = kb * (K1_ROWS_PER_BLK * SEQ);

        if (tid < K1_ROWS_PER_BLK * SEQ) sm.b.wbuf[tid] = s_words[wbase + tid];
        __syncthreads();

        if (tid == 0) {
            int all0 = 1;
            #pragma unroll
            for (int i = 1; i < K1_ROWS_PER_BLK * SEQ; i += 2)
                all0 &= (sm.b.wbuf[i] == 0u);
            sm.b.is64 = all0;
        }
        __syncthreads();

        const int is64 = sm.b.is64;
        if (tid < K1_ROWS_PER_BLK * SEQ) {
            int r = tid / SEQ, j = tid - r * SEQ;
            sm.b.toks[r][j] = is64 ? (int)s_words[2 * (wbase + tid)]
                                   : (int)sm.b.wbuf[tid];
        }
        __syncthreads();

        if (tid < K1_ROWS_PER_BLK * SEQ) {
            int r = tid / SEQ, j = tid - r * SEQ;
            int t = sm.b.toks[r][j];
            float k = 1.0f;
            for (int j2 = 0; j2 < j; j2++)
                if (sm.b.toks[r][j2] == t) { k = 0.0f; break; }
            sm.b.keep[r][j] = k;
        }
        __syncthreads();

        // gather: 2 rows x 2 halves x 64 col-threads; 8-deep load batches
        const int r    = tid >> 7;
        const int h    = (tid >> 6) & 1;
        const int c4   = (tid & 63) * 4;
        const int jb   = h * (SEQ / 2);       // 25 tokens per half
        const float* __restrict__ Wc = Wh + c4;
        const unsigned long long pol = mk_policy_el();

        float4 sa[8];
        #pragma unroll
        for (int q = 0; q < 8; q++) sa[q] = make_float4(0.f, 0.f, 0.f, 0.f);

        #pragma unroll
        for (int i = 0; i < 24; i += 8) {
            float4 v[8];
            float  kf[8];
            #pragma unroll
            for (int q = 0; q < 8; q++) {
                v[q]  = ldg_el(Wc + sm.b.toks[r][jb + i + q] * HID, pol);
                kf[q] = sm.b.keep[r][jb + i + q];
            }
            #pragma unroll
            for (int q = 0; q < 8; q++) {
                sa[q].x = fmaf(kf[q], v[q].x, sa[q].x);
                sa[q].y = fmaf(kf[q], v[q].y, sa[q].y);
                sa[q].z = fmaf(kf[q], v[q].z, sa[q].z);
                sa[q].w = fmaf(kf[q], v[q].w, sa[q].w);
            }
        }
        {   // tail token (i = 24)
            const float4 v = ldg_el(Wc + sm.b.toks[r][jb + 24] * HID, pol);
            const float kf = sm.b.keep[r][jb + 24];
            sa[0].x = fmaf(kf, v.x, sa[0].x); sa[0].y = fmaf(kf, v.y, sa[0].y);
            sa[0].z = fmaf(kf, v.z, sa[0].z); sa[0].w = fmaf(kf, v.w, sa[0].w);
        }

        float4 t;
        t.x = ((sa[0].x + sa[1].x) + (sa[2].x + sa[3].x)) +
              ((sa[4].x + sa[5].x) + (sa[6].x + sa[7].x));
        t.y = ((sa[0].y + sa[1].y) + (sa[2].y + sa[3].y)) +
              ((sa[4].y + sa[5].y) + (sa[6].y + sa[7].y));
        t.z = ((sa[0].z + sa[1].z) + (sa[2].z + sa[3].z)) +
              ((sa[4].z + sa[5].z) + (sa[6].z + sa[7].z));
        t.w = ((sa[0].w + sa[1].w) + (sa[2].w + sa[3].w)) +
              ((sa[4].w + sa[5].w) + (sa[6].w + sa[7].w));

        if (h == 1) *(float4*)&sm.b.part[r][c4] = t;
        __syncthreads();
        if (h == 0) {
            const float4 p  = *(const float4*)&sm.b.part[r][c4];
            const float4 bb = *(const float4*)(bh + c4);
            *(float4*)&g_bow_h[(kb * K1_ROWS_PER_BLK + r) * HID + c4] =
                make_float4(lky(t.x + p.x + bb.x), lky(t.y + p.y + bb.y),
                            lky(t.z + p.z + bb.z), lky(t.w + p.w + bb.w));
        }
    }
}

// ============================================================================
// K3 v5 (round-8, measured 10.7us incl combine): K-split epilogue.
// grid (128, 2 sides, 2 khalf) = 512 blocks.
// ============================================================================
#define EPB 16
#define HP  20

union EpSmem {
    float WeS[128][64];
    struct {
        float red[4][EPB][64];
        float predred[EPB * 10];
    } r;
};

__global__ __launch_bounds__(256) void epilogue_kernel(
    const float* __restrict__ We_bow, const float* __restrict__ Wp_bow,
    const float* __restrict__ We_beo, const float* __restrict__ Wp_beo)
{
    __shared__ __align__(16) float sh_t[128][HP];
    __shared__ EpSmem u;

    const int side = blockIdx.y;
    const int kh   = blockIdx.z;
    const int row0 = blockIdx.x * EPB;
    const int tid  = threadIdx.x;
    const int kg0  = kh * 128;

    const float* H  = side ? g_beo_h : g_bow_h;
    const float* We = side ? We_beo : We_bow;
    const float* Wp = side ? Wp_beo : Wp_bow;

    #pragma unroll
    for (int f = tid; f < EPB * 32; f += 256) {
        int r = f & 15, cq = f >> 4;
        float4 v = *(const float4*)&H[(row0 + r) * HID + kg0 + cq * 4];
        sh_t[cq * 4 + 0][r] = v.x;
        sh_t[cq * 4 + 1][r] = v.y;
        sh_t[cq * 4 + 2][r] = v.z;
        sh_t[cq * 4 + 3][r] = v.w;
    }
    #pragma unroll
    for (int f = tid; f < 128 * 16; f += 256) {
        int kr = f >> 4, nq = f & 15;
        *(float4*)&u.WeS[kr][nq * 4] =
            *(const float4*)&We[(kg0 + kr) * 64 + nq * 4];
    }
    __syncthreads();

    const int cg = tid & 15;
    const int rg = (tid >> 4) & 3;
    const int kp = tid >> 6;

    unsigned long long acc[4][2];
    #pragma unroll
    for (int r = 0; r < 4; r++) { acc[r][0] = 0ull; acc[r][1] = 0ull; }

    #pragma unroll 8
    for (int k = 0; k < 32; k++) {
        const int kk = kp * 32 + k;
        float4 hv = *(const float4*)&sh_t[kk][rg * 4];
        float4 wv = *(const float4*)&u.WeS[kk][cg * 4];
        unsigned long long pw0, pw1;
        asm("mov.b64 %0, {%1, %2};" : "=l"(pw0) : "f"(wv.x), "f"(wv.y));
        asm("mov.b64 %0, {%1, %2};" : "=l"(pw1) : "f"(wv.z), "f"(wv.w));
        unsigned long long ph0, ph1, ph2, ph3;
        asm("mov.b64 %0, {%1, %1};" : "=l"(ph0) : "f"(hv.x));
        asm("mov.b64 %0, {%1, %1};" : "=l"(ph1) : "f"(hv.y));
        asm("mov.b64 %0, {%1, %1};" : "=l"(ph2) : "f"(hv.z));
        asm("mov.b64 %0, {%1, %1};" : "=l"(ph3) : "f"(hv.w));
        asm("fma.rn.f32x2 %0, %1, %2, %0;" : "+l"(acc[0][0]) : "l"(ph0), "l"(pw0));
        asm("fma.rn.f32x2 %0, %1, %2, %0;" : "+l"(acc[0][1]) : "l"(ph0), "l"(pw1));
        asm("fma.rn.f32x2 %0, %1, %2, %0;" : "+l"(acc[1][0]) : "l"(ph1), "l"(pw0));
        asm("fma.rn.f32x2 %0, %1, %2, %0;" : "+l"(acc[1][1]) : "l"(ph1), "l"(pw1));
        asm("fma.rn.f32x2 %0, %1, %2, %0;" : "+l"(acc[2][0]) : "l"(ph2), "l"(pw0));
        asm("fma.rn.f32x2 %0, %1, %2, %0;" : "+l"(acc[2][1]) : "l"(ph2), "l"(pw1));
        asm("fma.rn.f32x2 %0, %1, %2, %0;" : "+l"(acc[3][0]) : "l"(ph3), "l"(pw0));
        asm("fma.rn.f32x2 %0, %1, %2, %0;" : "+l"(acc[3][1]) : "l"(ph3), "l"(pw1));
    }
    __syncthreads();

    #pragma unroll
    for (int r = 0; r < 4; r++) {
        float a0, a1, a2, a3;
        asm("mov.b64 {%0, %1}, %2;" : "=f"(a0), "=f"(a1) : "l"(acc[r][0]));
        asm("mov.b64 {%0, %1}, %2;" : "=f"(a2), "=f"(a3) : "l"(acc[r][1]));
        *(float4*)&u.r.red[kp][rg * 4 + r][cg * 4] = make_float4(a0, a1, a2, a3);
    }

    if (tid < EPB * 10) {
        int r   = tid / 10;
        int rem = tid - r * 10;
        int j   = rem % 5;
        int kq  = rem / 5;
        const int kb = kq * 64;
        float a0 = 0.f, a1 = 0.f, a2 = 0.f, a3 = 0.f;
        #pragma unroll 4
        for (int k = 0; k < 64; k += 4) {
            a0 = fmaf(sh_t[kb + k + 0][r], Wp[(kg0 + kb + k + 0) * 5 + j], a0);
            a1 = fmaf(sh_t[kb + k + 1][r], Wp[(kg0 + kb + k + 1) * 5 + j], a1);
            a2 = fmaf(sh_t[kb + k + 2][r], Wp[(kg0 + kb + k + 2) * 5 + j], a2);
            a3 = fmaf(sh_t[kb + k + 3][r], Wp[(kg0 + kb + k + 3) * 5 + j], a3);
        }
        u.r.predred[tid] = (a0 + a1) + (a2 + a3);
    }
    __syncthreads();

    float* P = &g_part[((size_t)(side * 2 + kh) * BATCH) * 72];
    {
        const int rr = tid >> 4;
        const int c4 = (tid & 15) * 4;
        float4 p0 = *(const float4*)&u.r.red[0][rr][c4];
        float4 p1 = *(const float4*)&u.r.red[1][rr][c4];
        float4 p2 = *(const float4*)&u.r.red[2][rr][c4];
        float4 p3 = *(const float4*)&u.r.red[3][rr][c4];
        *(float4*)&P[(row0 + rr) * 72 + c4] =
            make_float4((p0.x + p1.x) + (p2.x + p3.x),
                        (p0.y + p1.y) + (p2.y + p3.y),
                        (p0.z + p1.z) + (p2.z + p3.z),
                        (p0.w + p1.w) + (p2.w + p3.w));
    }
    if (tid < EPB * 5) {
        int r = tid / 5, j = tid - r * 5;
        P[(row0 + r) * 72 + 64 + j] =
            u.r.predred[r * 10 + j] + u.r.predred[r * 10 + 5 + j];
    }
}

// ============================================================================
// Combine kernel: out = part[kh=0] + part[kh=1] + bias. grid (552, 2).
// ============================================================================
__global__ __launch_bounds__(256) void combine_kernel(
    const float* __restrict__ be_bow, const float* __restrict__ bp_bow,
    const float* __restrict__ be_beo, const float* __restrict__ bp_beo,
    float* __restrict__ out)
{
    const int side = blockIdx.y;
    const int e    = blockIdx.x * 256 + threadIdx.x;
    if (e >= BATCH * 69) return;

    const float* P0 = &g_part[((size_t)(side * 2 + 0) * BATCH) * 72];
    const float* P1 = &g_part[((size_t)(side * 2 + 1) * BATCH) * 72];

    if (e < BATCH * 64) {
        int row = e >> 6, c = e & 63;
        float b = side ? be_beo[c] : be_bow[c];
        out[(side ? BATCH * 64 : 0) + e] =
            P0[row * 72 + c] + P1[row * 72 + c] + b;
    } else {
        int e2 = e - BATCH * 64;
        int row = e2 / 5, j = e2 - row * 5;
        float b = side ? bp_beo[j] : bp_bow[j];
        out[BATCH * 128 + side * BATCH * 5 + e2] =
            P0[row * 72 + 64 + j] + P1[row * 72 + 64 + j] + b;
    }
}

// ============================================================================
extern "C" void kernel_launch(void* const* d_in, const int* in_sizes, int n_in,
                              void* d_out, int out_size)
{
    const unsigned int* s_words = (const unsigned int*)d_in[0];
    const float* x        = (const float*)d_in[1];
    const float* W_bow_h  = (const float*)d_in[2];
    const float* b_bow_h  = (const float*)d_in[3];
    const float* W_bow_p  = (const float*)d_in[4];
    const float* b_bow_p  = (const float*)d_in[5];
    const float* W_bow_e  = (const float*)d_in[6];
    const float* b_bow_e  = (const float*)d_in[7];
    const float* W_beo_h  = (const float*)d_in[8];
    const float* b_beo_h  = (const float*)d_in[9];
    const float* W_beo_p  = (const float*)d_in[10];
    const float* b_beo_p  = (const float*)d_in[11];
    const float* W_beo_e  = (const float*)d_in[12];
    const float* b_beo_e  = (const float*)d_in[13];
    float* out = (float*)d_out;

    fused_hidden_kernel<<<K2_BLOCKS + K1_BLOCKS, 256>>>(
        s_words, W_bow_h, b_bow_h, x, W_beo_h, b_beo_h);

    dim3 g3(BATCH / EPB, 2, 2);
    epilogue_kernel<<<g3, 256>>>(W_bow_e, W_bow_p, W_beo_e, W_beo_p);

    dim3 g4((BATCH * 69 + 255) / 256, 2);
    combine_kernel<<<g4, 256>>>(b_bow_e, b_bow_p, b_beo_e, b_beo_p, out);
}